// round 1
// baseline (speedup 1.0000x reference)
#include <cuda_runtime.h>

#define Bb 256
#define Tt 256
#define Cc 384
#define Hh 64

// Scratch for projected q, k, v  (3 x 16.8 MB, __device__ globals per harness rules)
__device__ float g_q[Bb*Tt*Hh];
__device__ float g_k[Bb*Tt*Hh];
__device__ float g_v[Bb*Tt*Hh];

// ---------- packed f32x2 helpers (full-rate FMA path on sm_103a) ----------
static __device__ __forceinline__ unsigned long long pk2(float x, float y) {
    unsigned long long r;
    asm("mov.b64 %0, {%1, %2};" : "=l"(r) : "f"(x), "f"(y));
    return r;
}
static __device__ __forceinline__ void fma2(unsigned long long &d,
                                            unsigned long long a,
                                            unsigned long long b) {
    asm("fma.rn.f32x2 %0, %1, %2, %3;" : "=l"(d) : "l"(a), "l"(b), "l"(d));
}
static __device__ __forceinline__ void upk2(float &x, float &y, unsigned long long v) {
    asm("mov.b64 {%0, %1}, %2;" : "=f"(x), "=f"(y) : "l"(v));
}

// ============================================================================
// Kernel 1: fused QKV projection.  GEMM M=65536, K=384, N=192 (Wq|Wk|Wv).
// Block tile 64x192, 256 threads, per-thread 4x12 microtile (6 f32x2 pairs).
// ============================================================================
__global__ __launch_bounds__(256) void qkv_kernel(const float* __restrict__ x,
                                                  const float* __restrict__ Wq,
                                                  const float* __restrict__ Wk,
                                                  const float* __restrict__ Wv) {
    __shared__ float As[64 * 17];    // 64 rows x 16 k, pad 17
    __shared__ float Bs[16 * 196];   // 16 k x 192 cols, pad 196 (even -> f32x2 aligned)

    const int tid = threadIdx.x;
    const int tx = tid & 15;         // 0..15 -> 12 cols each
    const int ty = tid >> 4;         // 0..15 -> 4 rows each
    const int row0 = blockIdx.x * 64;

    unsigned long long acc[4][6];
#pragma unroll
    for (int i = 0; i < 4; i++)
#pragma unroll
        for (int j = 0; j < 6; j++) acc[i][j] = pk2(0.f, 0.f);

    const int ar = tid >> 2;            // A-load row 0..63
    const int ak = (tid & 3) * 4;       // A-load k offset

    for (int k0 = 0; k0 < Cc; k0 += 16) {
        __syncthreads();
        // A tile: one float4 per thread
        float4 av = *(const float4*)&x[(row0 + ar) * Cc + k0 + ak];
        As[ar * 17 + ak + 0] = av.x;
        As[ar * 17 + ak + 1] = av.y;
        As[ar * 17 + ak + 2] = av.z;
        As[ar * 17 + ak + 3] = av.w;
        // B tile: 3072 floats, 12 per thread
        for (int i = tid; i < 16 * 192; i += 256) {
            int kk = i / 192, col = i - kk * 192;
            const float* wp = (col < 64) ? Wq : (col < 128 ? Wk : Wv);
            Bs[kk * 196 + col] = wp[(k0 + kk) * 64 + (col & 63)];
        }
        __syncthreads();
#pragma unroll
        for (int kk = 0; kk < 16; kk++) {
            unsigned long long a2[4];
#pragma unroll
            for (int i = 0; i < 4; i++) {
                float v = As[(ty * 4 + i) * 17 + kk];
                a2[i] = pk2(v, v);
            }
#pragma unroll
            for (int j = 0; j < 6; j++) {
                float2 bv = *(const float2*)&Bs[kk * 196 + tx * 12 + 2 * j];
                unsigned long long b2 = pk2(bv.x, bv.y);
#pragma unroll
                for (int i = 0; i < 4; i++) fma2(acc[i][j], a2[i], b2);
            }
        }
    }

#pragma unroll
    for (int i = 0; i < 4; i++) {
        int r = row0 + ty * 4 + i;
#pragma unroll
        for (int j = 0; j < 6; j++) {
            float lo, hi;
            upk2(lo, hi, acc[i][j]);
            int col = tx * 12 + 2 * j;                       // even; pair never straddles 64
            float* dst = (col < 64) ? g_q : (col < 128 ? g_k : g_v);
            int c = col & 63;
            dst[r * 64 + c]     = lo;
            dst[r * 64 + c + 1] = hi;
        }
    }
}

// ============================================================================
// Kernel 2: causal attention with relative-position bias, one block per
// (batch, 64-query tile).  Two-pass softmax over the full (<=256) key range,
// scores live in shared memory.  256 threads.
// Shared layout (floats):
//   Qs[64*65]  Sf[64*257]  KV[64*66]  bias[64*4]  rowsum[64]   = 25152 f = 98.25 KB
// ============================================================================
__global__ __launch_bounds__(256) void attn_kernel(const float* __restrict__ relk,
                                                   const float* __restrict__ relv,
                                                   float* __restrict__ out) {
    extern __shared__ float sm[];
    float* Qs     = sm;                  // [64][65]
    float* Sf     = Qs + 64 * 65;        // [64][257]
    float* KV     = Sf + 64 * 257;       // [64][66]  (K^T in phase 1, V in phase 3)
    float* bias   = KV + 64 * 66;        // [64][4]
    float* rowsum = bias + 64 * 4;       // [64]

    const int tid = threadIdx.x;
    const int b    = blockIdx.x >> 2;
    const int tile = 3 - (blockIdx.x & 3);   // launch heavy tiles first
    const int t0   = tile * 64;
    const int nchunks = tile + 1;

    const float* qb = g_q + b * Tt * Hh;
    const float* kb = g_k + b * Tt * Hh;
    const float* vb = g_v + b * Tt * Hh;

    // ---- load Q tile ----
    for (int i = tid; i < 64 * 64; i += 256) {
        int r = i >> 6, h = i & 63;
        Qs[r * 65 + h] = qb[(t0 + r) * 64 + h];
    }
    __syncthreads();

    // ---- relative-position bias: bias[r][d] = q[r] . rel_k[d], d=0..3 ----
    {
        int r = tid >> 2, d = tid & 3;
        float s = 0.f;
#pragma unroll 16
        for (int h = 0; h < 64; h++) s += Qs[r * 65 + h] * relk[d * 64 + h];
        bias[r * 4 + d] = s;
    }

    const int tx = tid & 15;   // 4 cols each
    const int ty = tid >> 4;   // 4 rows each

    // ---- phase 1: S = Q K^T + bias, masked, scaled, into Sf ----
    for (int c = 0; c < nchunks; c++) {
        __syncthreads();
        for (int i = tid; i < 64 * 64; i += 256) {     // load K chunk transposed
            int sp = i >> 6, h = i & 63;
            KV[h * 66 + sp] = kb[(c * 64 + sp) * 64 + h];
        }
        __syncthreads();

        unsigned long long acc2[4][2];
#pragma unroll
        for (int i = 0; i < 4; i++) { acc2[i][0] = pk2(0.f, 0.f); acc2[i][1] = pk2(0.f, 0.f); }

#pragma unroll 8
        for (int h = 0; h < 64; h++) {
            unsigned long long a2[4];
#pragma unroll
            for (int i = 0; i < 4; i++) {
                float v = Qs[(ty * 4 + i) * 65 + h];
                a2[i] = pk2(v, v);
            }
#pragma unroll
            for (int j = 0; j < 2; j++) {
                float2 bv = *(const float2*)&KV[h * 66 + tx * 4 + 2 * j];
                unsigned long long b2 = pk2(bv.x, bv.y);
#pragma unroll
                for (int i = 0; i < 4; i++) fma2(acc2[i][j], a2[i], b2);
            }
        }

#pragma unroll
        for (int i = 0; i < 4; i++) {
            int r = ty * 4 + i;
            int t = t0 + r;
#pragma unroll
            for (int j = 0; j < 2; j++) {
                float lo, hi;
                upk2(lo, hi, acc2[i][j]);
                int s0 = c * 64 + tx * 4 + 2 * j;
#pragma unroll
                for (int e = 0; e < 2; e++) {
                    int s = s0 + e;
                    float raw = e ? hi : lo;
                    float val;
                    if (s > t) val = -1e30f;
                    else {
                        int d = s - t + 3; if (d < 0) d = 0;
                        val = (raw + bias[r * 4 + d]) * 0.125f;   // /sqrt(64)
                    }
                    Sf[r * 257 + s] = val;
                }
            }
        }
    }
    __syncthreads();

    // ---- phase 2: row softmax (unnormalized exp kept in Sf, sum in rowsum) ----
    {
        int warp = tid >> 5, lane = tid & 31;
        int nS = nchunks * 64;
        for (int rr = 0; rr < 8; rr++) {
            int r = warp * 8 + rr;
            float* Srow = &Sf[r * 257];
            float m = -1e30f;
            for (int s = lane; s < nS; s += 32) m = fmaxf(m, Srow[s]);
#pragma unroll
            for (int o = 16; o; o >>= 1) m = fmaxf(m, __shfl_xor_sync(~0u, m, o));
            float l = 0.f;
            for (int s = lane; s < nS; s += 32) {
                float e = __expf(Srow[s] - m);
                Srow[s] = e;
                l += e;
            }
#pragma unroll
            for (int o = 16; o; o >>= 1) l += __shfl_xor_sync(~0u, l, o);
            if (lane == 0) rowsum[r] = l;
        }
    }

    // ---- phase 3: O = P V (unnormalized) ----
    unsigned long long o2[4][2];
#pragma unroll
    for (int i = 0; i < 4; i++) { o2[i][0] = pk2(0.f, 0.f); o2[i][1] = pk2(0.f, 0.f); }

    for (int c = 0; c < nchunks; c++) {
        __syncthreads();
        for (int i = tid; i < 64 * 64; i += 256) {     // load V chunk (natural layout)
            int sp = i >> 6, h = i & 63;
            KV[sp * 66 + h] = vb[(c * 64 + sp) * 64 + h];
        }
        __syncthreads();
#pragma unroll 8
        for (int sp = 0; sp < 64; sp++) {
            unsigned long long a2[4];
#pragma unroll
            for (int i = 0; i < 4; i++) {
                float p = Sf[(ty * 4 + i) * 257 + c * 64 + sp];
                a2[i] = pk2(p, p);
            }
#pragma unroll
            for (int j = 0; j < 2; j++) {
                float2 bv = *(const float2*)&KV[sp * 66 + tx * 4 + 2 * j];
                unsigned long long b2 = pk2(bv.x, bv.y);
#pragma unroll
                for (int i = 0; i < 4; i++) fma2(o2[i][j], a2[i], b2);
            }
        }
    }

    // ---- epilogue: normalize, add collapsed rel_v correction, store ----
#pragma unroll
    for (int i = 0; i < 4; i++) {
        int r = ty * 4 + i;
        int t = t0 + r;
        float inv = 1.f / rowsum[r];
        float pt = Sf[r * 257 + t] * inv;                       // s = t   -> rv[3]
        float p1 = (t >= 1) ? Sf[r * 257 + t - 1] * inv : 0.f;  // s = t-1 -> rv[2]
        float p2 = (t >= 2) ? Sf[r * 257 + t - 2] * inv : 0.f;  // s = t-2 -> rv[1]
        float aw0 = 1.f - pt - p1 - p2;                          // all s <= t-3 -> rv[0]
#pragma unroll
        for (int j = 0; j < 2; j++) {
            float lo, hi;
            upk2(lo, hi, o2[i][j]);
            int h = tx * 4 + 2 * j;
            float r0 = lo * inv + aw0 * relv[h]     + p2 * relv[64 + h]
                                + p1 * relv[128 + h] + pt * relv[192 + h];
            float r1 = hi * inv + aw0 * relv[h + 1] + p2 * relv[64 + h + 1]
                                + p1 * relv[128 + h + 1] + pt * relv[192 + h + 1];
            out[(b * Tt + t) * 64 + h]     = r0;
            out[(b * Tt + t) * 64 + h + 1] = r1;
        }
    }
}

// ============================================================================
extern "C" void kernel_launch(void* const* d_in, const int* in_sizes, int n_in,
                              void* d_out, int out_size) {
    const float* x    = (const float*)d_in[0];
    const float* Wq   = (const float*)d_in[1];
    const float* Wk   = (const float*)d_in[2];
    const float* Wv   = (const float*)d_in[3];
    const float* relk = (const float*)d_in[4];
    const float* relv = (const float*)d_in[5];
    float* out = (float*)d_out;

    qkv_kernel<<<(Bb * Tt) / 64, 256>>>(x, Wq, Wk, Wv);

    int smem_bytes = (64 * 65 + 64 * 257 + 64 * 66 + 64 * 4 + 64) * (int)sizeof(float);
    cudaFuncSetAttribute(attn_kernel, cudaFuncAttributeMaxDynamicSharedMemorySize, smem_bytes);
    attn_kernel<<<Bb * 4, 256, smem_bytes>>>(relk, relv, out);
}

// round 3
// speedup vs baseline: 1.6750x; 1.6750x over previous
#include <cuda_runtime.h>
#include <cuda_bf16.h>
#include <cstdint>

#define Bb 256
#define Tt 256
#define Cc 384
#define Hh 64
#define NB 192   // q|k|v output columns

// Scratch (device globals per harness rules)
__device__ float g_q[Bb*Tt*Hh];
__device__ float g_k[Bb*Tt*Hh];
__device__ float g_v[Bb*Tt*Hh];
__device__ __align__(16) __nv_bfloat16 g_bh[NB*Cc];   // W^T hi, K-major rows
__device__ __align__(16) __nv_bfloat16 g_bl[NB*Cc];   // W^T lo

// ============================================================================
// Kernel 0: split W into K-major bf16 hi/lo:  g_b*[n*Cc + k]
// ============================================================================
__global__ __launch_bounds__(256) void prep_w(const float* __restrict__ Wq,
                                              const float* __restrict__ Wk,
                                              const float* __restrict__ Wv) {
    int j = blockIdx.x * 256 + threadIdx.x;     // j = k*NB + n  (coalesced reads)
    if (j >= Cc * NB) return;
    int k = j / NB, n = j - k * NB;
    const float* w = (n < 64) ? Wq : ((n < 128) ? Wk : Wv);
    float v = w[k * 64 + (n & 63)];
    __nv_bfloat16 hi = __float2bfloat16(v);
    float lo = v - __bfloat162float(hi);
    g_bh[n * Cc + k] = hi;
    g_bl[n * Cc + k] = __float2bfloat16(lo);
}

// ---------------- HMMA helper (sm_80+ feature, valid on sm_103 base) --------
static __device__ __forceinline__ void hmma(float* c, const uint32_t* a, const uint32_t* b) {
    asm volatile(
        "mma.sync.aligned.m16n8k16.row.col.f32.bf16.bf16.f32 "
        "{%0,%1,%2,%3}, {%4,%5,%6,%7}, {%8,%9}, {%0,%1,%2,%3};"
        : "+f"(c[0]), "+f"(c[1]), "+f"(c[2]), "+f"(c[3])
        : "r"(a[0]), "r"(a[1]), "r"(a[2]), "r"(a[3]), "r"(b[0]), "r"(b[1]));
}
static __device__ __forceinline__ uint32_t lds32(const __nv_bfloat16* p) {
    return *(const uint32_t*)p;
}

// ============================================================================
// Kernel 1: QKV projection, split-precision bf16 HMMA, fp32 accumulate.
// CTA tile M=128 x N=192, K=384 in 6 chunks of 64 staged in smem.
// Warp grid 4(M) x 2(N): warp tile 32x96 = 2 m16-frags x 12 n8-frags.
// Passes per chunk: hi*hi, lo*hi, hi*lo.
// smem rows padded to 72 bf16 -> conflict-free fragment loads.
// ============================================================================
#define ASTR 72
__global__ __launch_bounds__(256) void qkv_hmma(const float* __restrict__ x) {
    extern __shared__ __nv_bfloat16 sm[];
    __nv_bfloat16* Ah = sm;                    // 128*72
    __nv_bfloat16* Al = Ah + 128 * ASTR;
    __nv_bfloat16* Bh = Al + 128 * ASTR;       // 192*72
    __nv_bfloat16* Bl = Bh + 192 * ASTR;

    const int tid  = threadIdx.x;
    const int wid  = tid >> 5, lane = tid & 31;
    const int g    = lane >> 2, t = lane & 3;   // groupID / threadInGroup
    const int wm   = wid & 3;                   // 0..3 -> 32 rows each
    const int wn   = wid >> 2;                  // 0..1 -> 96 cols each
    const int row0 = blockIdx.x * 128;

    float acc[2][12][4];
#pragma unroll
    for (int mi = 0; mi < 2; mi++)
#pragma unroll
        for (int ni = 0; ni < 12; ni++)
#pragma unroll
            for (int e = 0; e < 4; e++) acc[mi][ni][e] = 0.f;

    for (int c = 0; c < 6; c++) {
        const int k0 = c * 64;
        __syncthreads();
        // ---- A chunk: load x fp32, split bf16 hi/lo ----
        for (int i = tid; i < 2048; i += 256) {
            int r = i >> 4, seg = i & 15;               // seg = 4-float group
            float4 v = *(const float4*)&x[(size_t)(row0 + r) * Cc + k0 + seg * 4];
            __nv_bfloat162 h0 = __floats2bfloat162_rn(v.x, v.y);
            __nv_bfloat162 h1 = __floats2bfloat162_rn(v.z, v.w);
            float2 hf0 = __bfloat1622float2(h0), hf1 = __bfloat1622float2(h1);
            __nv_bfloat162 l0 = __floats2bfloat162_rn(v.x - hf0.x, v.y - hf0.y);
            __nv_bfloat162 l1 = __floats2bfloat162_rn(v.z - hf1.x, v.w - hf1.y);
            uint2 hp, lp;
            hp.x = *(uint32_t*)&h0; hp.y = *(uint32_t*)&h1;
            lp.x = *(uint32_t*)&l0; lp.y = *(uint32_t*)&l1;
            *(uint2*)&Ah[r * ASTR + seg * 4] = hp;
            *(uint2*)&Al[r * ASTR + seg * 4] = lp;
        }
        // ---- B chunk: coalesced copy of pre-split weights (n-major) ----
        for (int i = tid; i < 1536; i += 256) {
            int n = i >> 3, seg = i & 7;                // seg = 8-bf16 group
            size_t gofs = (size_t)n * Cc + k0 + seg * 8;
            uint4 hv = *(const uint4*)&g_bh[gofs];
            uint4 lv = *(const uint4*)&g_bl[gofs];
            *(uint4*)&Bh[n * ASTR + seg * 8] = hv;
            *(uint4*)&Bl[n * ASTR + seg * 8] = lv;
        }
        __syncthreads();

#pragma unroll
        for (int p = 0; p < 3; p++) {
            const __nv_bfloat16* Ap = (p == 1) ? Al : Ah;
            const __nv_bfloat16* Bp = (p == 2) ? Bl : Bh;
#pragma unroll
            for (int s = 0; s < 4; s++) {
                const int ka = s * 16 + 2 * t;
                uint32_t a[2][4];
#pragma unroll
                for (int mi = 0; mi < 2; mi++) {
                    int r = wm * 32 + mi * 16 + g;
                    a[mi][0] = lds32(Ap + r * ASTR + ka);
                    a[mi][1] = lds32(Ap + (r + 8) * ASTR + ka);
                    a[mi][2] = lds32(Ap + r * ASTR + ka + 8);
                    a[mi][3] = lds32(Ap + (r + 8) * ASTR + ka + 8);
                }
                uint32_t b[12][2];
#pragma unroll
                for (int ni = 0; ni < 12; ni++) {
                    int n = wn * 96 + ni * 8 + g;
                    b[ni][0] = lds32(Bp + n * ASTR + ka);
                    b[ni][1] = lds32(Bp + n * ASTR + ka + 8);
                }
#pragma unroll
                for (int mi = 0; mi < 2; mi++)
#pragma unroll
                    for (int ni = 0; ni < 12; ni++)
                        hmma(acc[mi][ni], a[mi], b[ni]);
            }
        }
    }

    // ---- epilogue: scatter fp32 accumulators to g_q / g_k / g_v ----
#pragma unroll
    for (int mi = 0; mi < 2; mi++) {
        int r = row0 + wm * 32 + mi * 16 + g;
#pragma unroll
        for (int ni = 0; ni < 12; ni++) {
            int col = wn * 96 + ni * 8 + 2 * t;
            float* dst = (col < 64) ? g_q : ((col < 128) ? g_k : g_v);
            int cc = col & 63;
            float2 v01 = make_float2(acc[mi][ni][0], acc[mi][ni][1]);
            float2 v23 = make_float2(acc[mi][ni][2], acc[mi][ni][3]);
            *(float2*)&dst[(size_t)r * 64 + cc]       = v01;
            *(float2*)&dst[(size_t)(r + 8) * 64 + cc] = v23;
        }
    }
}

// ============================================================================
// Kernel 2: causal attention with relative-position bias (round-1 version)
// ============================================================================
static __device__ __forceinline__ unsigned long long pk2(float x, float y) {
    unsigned long long r;
    asm("mov.b64 %0, {%1, %2};" : "=l"(r) : "f"(x), "f"(y));
    return r;
}
static __device__ __forceinline__ void fma2(unsigned long long &d,
                                            unsigned long long a,
                                            unsigned long long b) {
    asm("fma.rn.f32x2 %0, %1, %2, %3;" : "=l"(d) : "l"(a), "l"(b), "l"(d));
}
static __device__ __forceinline__ void upk2(float &x, float &y, unsigned long long v) {
    asm("mov.b64 {%0, %1}, %2;" : "=f"(x), "=f"(y) : "l"(v));
}

__global__ __launch_bounds__(256) void attn_kernel(const float* __restrict__ relk,
                                                   const float* __restrict__ relv,
                                                   float* __restrict__ out) {
    extern __shared__ float smf[];
    float* Qs     = smf;                 // [64][65]
    float* Sf     = Qs + 64 * 65;        // [64][257]
    float* KV     = Sf + 64 * 257;       // [64][66]
    float* bias   = KV + 64 * 66;        // [64][4]
    float* rowsum = bias + 64 * 4;       // [64]

    const int tid = threadIdx.x;
    const int b    = blockIdx.x >> 2;
    const int tile = 3 - (blockIdx.x & 3);
    const int t0   = tile * 64;
    const int nchunks = tile + 1;

    const float* qb = g_q + b * Tt * Hh;
    const float* kb = g_k + b * Tt * Hh;
    const float* vb = g_v + b * Tt * Hh;

    for (int i = tid; i < 64 * 64; i += 256) {
        int r = i >> 6, h = i & 63;
        Qs[r * 65 + h] = qb[(t0 + r) * 64 + h];
    }
    __syncthreads();

    {
        int r = tid >> 2, d = tid & 3;
        float s = 0.f;
#pragma unroll 16
        for (int h = 0; h < 64; h++) s += Qs[r * 65 + h] * relk[d * 64 + h];
        bias[r * 4 + d] = s;
    }

    const int tx = tid & 15;
    const int ty = tid >> 4;

    for (int c = 0; c < nchunks; c++) {
        __syncthreads();
        for (int i = tid; i < 64 * 64; i += 256) {
            int sp = i >> 6, h = i & 63;
            KV[h * 66 + sp] = kb[(c * 64 + sp) * 64 + h];
        }
        __syncthreads();

        unsigned long long acc2[4][2];
#pragma unroll
        for (int i = 0; i < 4; i++) { acc2[i][0] = pk2(0.f, 0.f); acc2[i][1] = pk2(0.f, 0.f); }

#pragma unroll 8
        for (int h = 0; h < 64; h++) {
            unsigned long long a2[4];
#pragma unroll
            for (int i = 0; i < 4; i++) {
                float v = Qs[(ty * 4 + i) * 65 + h];
                a2[i] = pk2(v, v);
            }
#pragma unroll
            for (int j = 0; j < 2; j++) {
                float2 bv = *(const float2*)&KV[h * 66 + tx * 4 + 2 * j];
                unsigned long long b2 = pk2(bv.x, bv.y);
#pragma unroll
                for (int i = 0; i < 4; i++) fma2(acc2[i][j], a2[i], b2);
            }
        }

#pragma unroll
        for (int i = 0; i < 4; i++) {
            int r = ty * 4 + i;
            int t = t0 + r;
#pragma unroll
            for (int j = 0; j < 2; j++) {
                float lo, hi;
                upk2(lo, hi, acc2[i][j]);
                int s0 = c * 64 + tx * 4 + 2 * j;
#pragma unroll
                for (int e = 0; e < 2; e++) {
                    int s = s0 + e;
                    float raw = e ? hi : lo;
                    float val;
                    if (s > t) val = -1e30f;
                    else {
                        int d = s - t + 3; if (d < 0) d = 0;
                        val = (raw + bias[r * 4 + d]) * 0.125f;
                    }
                    Sf[r * 257 + s] = val;
                }
            }
        }
    }
    __syncthreads();

    {
        int warp = tid >> 5, lane = tid & 31;
        int nS = nchunks * 64;
        for (int rr = 0; rr < 8; rr++) {
            int r = warp * 8 + rr;
            float* Srow = &Sf[r * 257];
            float m = -1e30f;
            for (int s = lane; s < nS; s += 32) m = fmaxf(m, Srow[s]);
#pragma unroll
            for (int o = 16; o; o >>= 1) m = fmaxf(m, __shfl_xor_sync(~0u, m, o));
            float l = 0.f;
            for (int s = lane; s < nS; s += 32) {
                float e = __expf(Srow[s] - m);
                Srow[s] = e;
                l += e;
            }
#pragma unroll
            for (int o = 16; o; o >>= 1) l += __shfl_xor_sync(~0u, l, o);
            if (lane == 0) rowsum[r] = l;
        }
    }

    unsigned long long o2[4][2];
#pragma unroll
    for (int i = 0; i < 4; i++) { o2[i][0] = pk2(0.f, 0.f); o2[i][1] = pk2(0.f, 0.f); }

    for (int c = 0; c < nchunks; c++) {
        __syncthreads();
        for (int i = tid; i < 64 * 64; i += 256) {
            int sp = i >> 6, h = i & 63;
            KV[sp * 66 + h] = vb[(c * 64 + sp) * 64 + h];
        }
        __syncthreads();
#pragma unroll 8
        for (int sp = 0; sp < 64; sp++) {
            unsigned long long a2[4];
#pragma unroll
            for (int i = 0; i < 4; i++) {
                float p = Sf[(ty * 4 + i) * 257 + c * 64 + sp];
                a2[i] = pk2(p, p);
            }
#pragma unroll
            for (int j = 0; j < 2; j++) {
                float2 bv = *(const float2*)&KV[sp * 66 + tx * 4 + 2 * j];
                unsigned long long b2 = pk2(bv.x, bv.y);
#pragma unroll
                for (int i = 0; i < 4; i++) fma2(o2[i][j], a2[i], b2);
            }
        }
    }

#pragma unroll
    for (int i = 0; i < 4; i++) {
        int r = ty * 4 + i;
        int t = t0 + r;
        float inv = 1.f / rowsum[r];
        float pt = Sf[r * 257 + t] * inv;
        float p1 = (t >= 1) ? Sf[r * 257 + t - 1] * inv : 0.f;
        float p2 = (t >= 2) ? Sf[r * 257 + t - 2] * inv : 0.f;
        float aw0 = 1.f - pt - p1 - p2;
#pragma unroll
        for (int j = 0; j < 2; j++) {
            float lo, hi;
            upk2(lo, hi, o2[i][j]);
            int h = tx * 4 + 2 * j;
            float r0 = lo * inv + aw0 * relv[h]     + p2 * relv[64 + h]
                                + p1 * relv[128 + h] + pt * relv[192 + h];
            float r1 = hi * inv + aw0 * relv[h + 1] + p2 * relv[64 + h + 1]
                                + p1 * relv[128 + h + 1] + pt * relv[192 + h + 1];
            out[(b * Tt + t) * 64 + h]     = r0;
            out[(b * Tt + t) * 64 + h + 1] = r1;
        }
    }
}

// ============================================================================
extern "C" void kernel_launch(void* const* d_in, const int* in_sizes, int n_in,
                              void* d_out, int out_size) {
    const float* x    = (const float*)d_in[0];
    const float* Wq   = (const float*)d_in[1];
    const float* Wk   = (const float*)d_in[2];
    const float* Wv   = (const float*)d_in[3];
    const float* relk = (const float*)d_in[4];
    const float* relv = (const float*)d_in[5];
    float* out = (float*)d_out;

    prep_w<<<(Cc * NB + 255) / 256, 256>>>(Wq, Wk, Wv);

    int gemm_smem = (2 * 128 * ASTR + 2 * 192 * ASTR) * (int)sizeof(__nv_bfloat16); // 92160 B
    cudaFuncSetAttribute(qkv_hmma, cudaFuncAttributeMaxDynamicSharedMemorySize, gemm_smem);
    qkv_hmma<<<(Bb * Tt) / 128, 256, gemm_smem>>>(x);

    int smem_bytes = (64 * 65 + 64 * 257 + 64 * 66 + 64 * 4 + 64) * (int)sizeof(float);
    cudaFuncSetAttribute(attn_kernel, cudaFuncAttributeMaxDynamicSharedMemorySize, smem_bytes);
    attn_kernel<<<Bb * 4, 256, smem_bytes>>>(relk, relv, out);
}

// round 4
// speedup vs baseline: 3.5357x; 2.1109x over previous
#include <cuda_runtime.h>
#include <cuda_bf16.h>
#include <cstdint>

#define Bb 256
#define Tt 256
#define Cc 384
#define Hh 64
#define NB 192

// q pre-scale: 1/sqrt(64) * log2(e)  -> scores come out in exp2 domain
#define SCL 0.18033688011112042f

// Scratch (device globals per harness rules). q/k: [b][t][h]; vT: [b][h][t]
__device__ __align__(16) __nv_bfloat16 g_qh[Bb*Tt*Hh];
__device__ __align__(16) __nv_bfloat16 g_ql[Bb*Tt*Hh];
__device__ __align__(16) __nv_bfloat16 g_kh[Bb*Tt*Hh];
__device__ __align__(16) __nv_bfloat16 g_kl[Bb*Tt*Hh];
__device__ __align__(16) __nv_bfloat16 g_vth[Bb*Tt*Hh];
__device__ __align__(16) __nv_bfloat16 g_vtl[Bb*Tt*Hh];
__device__ __align__(16) __nv_bfloat16 g_bh[NB*Cc];   // W^T hi, K-major rows
__device__ __align__(16) __nv_bfloat16 g_bl[NB*Cc];   // W^T lo

// ============================================================================
// Kernel 0: split W into K-major bf16 hi/lo
// ============================================================================
__global__ __launch_bounds__(256) void prep_w(const float* __restrict__ Wq,
                                              const float* __restrict__ Wk,
                                              const float* __restrict__ Wv) {
    int j = blockIdx.x * 256 + threadIdx.x;
    if (j >= Cc * NB) return;
    int k = j / NB, n = j - k * NB;
    const float* w = (n < 64) ? Wq : ((n < 128) ? Wk : Wv);
    float v = w[k * 64 + (n & 63)];
    __nv_bfloat16 hi = __float2bfloat16(v);
    float lo = v - __bfloat162float(hi);
    g_bh[n * Cc + k] = hi;
    g_bl[n * Cc + k] = __float2bfloat16(lo);
}

// ---------------- HMMA + misc helpers ----------------
static __device__ __forceinline__ void hmma(float* c, const uint32_t* a, const uint32_t* b) {
    asm volatile(
        "mma.sync.aligned.m16n8k16.row.col.f32.bf16.bf16.f32 "
        "{%0,%1,%2,%3}, {%4,%5,%6,%7}, {%8,%9}, {%0,%1,%2,%3};"
        : "+f"(c[0]), "+f"(c[1]), "+f"(c[2]), "+f"(c[3])
        : "r"(a[0]), "r"(a[1]), "r"(a[2]), "r"(a[3]), "r"(b[0]), "r"(b[1]));
}
static __device__ __forceinline__ uint32_t lds32(const __nv_bfloat16* p) {
    return *(const uint32_t*)p;
}
static __device__ __forceinline__ float ex2(float x) {
    float r;
    asm("ex2.approx.ftz.f32 %0, %1;" : "=f"(r) : "f"(x));
    return r;
}
static __device__ __forceinline__ uint32_t b2u(__nv_bfloat162 v) {
    return *(uint32_t*)&v;
}

// ============================================================================
// Kernel 1: QKV projection, split-precision bf16 HMMA (proven mainloop).
// Epilogue: emit bf16 hi/lo; q pre-scaled; v transposed [b][h][t].
// ============================================================================
#define ASTR 72
__global__ __launch_bounds__(256) void qkv_hmma(const float* __restrict__ x) {
    extern __shared__ __nv_bfloat16 sm[];
    __nv_bfloat16* Ah = sm;
    __nv_bfloat16* Al = Ah + 128 * ASTR;
    __nv_bfloat16* Bh = Al + 128 * ASTR;
    __nv_bfloat16* Bl = Bh + 192 * ASTR;

    const int tid  = threadIdx.x;
    const int wid  = tid >> 5, lane = tid & 31;
    const int g    = lane >> 2, t = lane & 3;
    const int wm   = wid & 3;
    const int wn   = wid >> 2;
    const int row0 = blockIdx.x * 128;

    float acc[2][12][4];
#pragma unroll
    for (int mi = 0; mi < 2; mi++)
#pragma unroll
        for (int ni = 0; ni < 12; ni++)
#pragma unroll
            for (int e = 0; e < 4; e++) acc[mi][ni][e] = 0.f;

    for (int c = 0; c < 6; c++) {
        const int k0 = c * 64;
        __syncthreads();
        for (int i = tid; i < 2048; i += 256) {
            int r = i >> 4, seg = i & 15;
            float4 v = *(const float4*)&x[(size_t)(row0 + r) * Cc + k0 + seg * 4];
            __nv_bfloat162 h0 = __floats2bfloat162_rn(v.x, v.y);
            __nv_bfloat162 h1 = __floats2bfloat162_rn(v.z, v.w);
            float2 hf0 = __bfloat1622float2(h0), hf1 = __bfloat1622float2(h1);
            __nv_bfloat162 l0 = __floats2bfloat162_rn(v.x - hf0.x, v.y - hf0.y);
            __nv_bfloat162 l1 = __floats2bfloat162_rn(v.z - hf1.x, v.w - hf1.y);
            uint2 hp, lp;
            hp.x = *(uint32_t*)&h0; hp.y = *(uint32_t*)&h1;
            lp.x = *(uint32_t*)&l0; lp.y = *(uint32_t*)&l1;
            *(uint2*)&Ah[r * ASTR + seg * 4] = hp;
            *(uint2*)&Al[r * ASTR + seg * 4] = lp;
        }
        for (int i = tid; i < 1536; i += 256) {
            int n = i >> 3, seg = i & 7;
            size_t gofs = (size_t)n * Cc + k0 + seg * 8;
            uint4 hv = *(const uint4*)&g_bh[gofs];
            uint4 lv = *(const uint4*)&g_bl[gofs];
            *(uint4*)&Bh[n * ASTR + seg * 8] = hv;
            *(uint4*)&Bl[n * ASTR + seg * 8] = lv;
        }
        __syncthreads();

#pragma unroll
        for (int p = 0; p < 3; p++) {
            const __nv_bfloat16* Ap = (p == 1) ? Al : Ah;
            const __nv_bfloat16* Bp = (p == 2) ? Bl : Bh;
#pragma unroll
            for (int s = 0; s < 4; s++) {
                const int ka = s * 16 + 2 * t;
                uint32_t a[2][4];
#pragma unroll
                for (int mi = 0; mi < 2; mi++) {
                    int r = wm * 32 + mi * 16 + g;
                    a[mi][0] = lds32(Ap + r * ASTR + ka);
                    a[mi][1] = lds32(Ap + (r + 8) * ASTR + ka);
                    a[mi][2] = lds32(Ap + r * ASTR + ka + 8);
                    a[mi][3] = lds32(Ap + (r + 8) * ASTR + ka + 8);
                }
                uint32_t b[12][2];
#pragma unroll
                for (int ni = 0; ni < 12; ni++) {
                    int n = wn * 96 + ni * 8 + g;
                    b[ni][0] = lds32(Bp + n * ASTR + ka);
                    b[ni][1] = lds32(Bp + n * ASTR + ka + 8);
                }
#pragma unroll
                for (int mi = 0; mi < 2; mi++)
#pragma unroll
                    for (int ni = 0; ni < 12; ni++)
                        hmma(acc[mi][ni], a[mi], b[ni]);
            }
        }
    }

    // ---- epilogue: split to bf16 hi/lo and scatter ----
#pragma unroll
    for (int mi = 0; mi < 2; mi++) {
        int r = row0 + wm * 32 + mi * 16 + g;
        int bI = r >> 8, tt = r & 255;
#pragma unroll
        for (int ni = 0; ni < 12; ni++) {
            int col = wn * 96 + ni * 8 + 2 * t;
            float v00 = acc[mi][ni][0], v01 = acc[mi][ni][1];
            float v10 = acc[mi][ni][2], v11 = acc[mi][ni][3];
            if (col < 64) { v00 *= SCL; v01 *= SCL; v10 *= SCL; v11 *= SCL; }
            __nv_bfloat162 h0 = __floats2bfloat162_rn(v00, v01);
            float2 hf0 = __bfloat1622float2(h0);
            __nv_bfloat162 l0 = __floats2bfloat162_rn(v00 - hf0.x, v01 - hf0.y);
            __nv_bfloat162 h1 = __floats2bfloat162_rn(v10, v11);
            float2 hf1 = __bfloat1622float2(h1);
            __nv_bfloat162 l1 = __floats2bfloat162_rn(v10 - hf1.x, v11 - hf1.y);
            if (col < 128) {
                __nv_bfloat16* dh = (col < 64) ? g_qh : g_kh;
                __nv_bfloat16* dl = (col < 64) ? g_ql : g_kl;
                int cc = col & 63;
                *(__nv_bfloat162*)&dh[(size_t)r * 64 + cc]       = h0;
                *(__nv_bfloat162*)&dl[(size_t)r * 64 + cc]       = l0;
                *(__nv_bfloat162*)&dh[(size_t)(r + 8) * 64 + cc] = h1;
                *(__nv_bfloat162*)&dl[(size_t)(r + 8) * 64 + cc] = l1;
            } else {
                int cc = col - 128;
                size_t base = (size_t)bI * 16384 + (size_t)cc * 256;
                g_vth[base + tt]           = h0.x;
                g_vth[base + 256 + tt]     = h0.y;
                g_vtl[base + tt]           = l0.x;
                g_vtl[base + 256 + tt]     = l0.y;
                g_vth[base + tt + 8]       = h1.x;
                g_vth[base + 256 + tt + 8] = h1.y;
                g_vtl[base + tt + 8]       = l1.x;
                g_vtl[base + 256 + tt + 8] = l1.y;
            }
        }
    }
}

// ============================================================================
// Kernel 2: flash-style causal attention with relative-position terms.
// 128 threads = 4 warps; warp w owns 16 query rows. Register-resident
// Q-frags / P-frags / O-accum; online softmax in exp2 domain.
// ============================================================================
#define QSTR 72
__global__ __launch_bounds__(128, 3) void attn_flash(const float* __restrict__ relk,
                                                     const float* __restrict__ relv,
                                                     float* __restrict__ out) {
    extern __shared__ char smraw[];
    __nv_bfloat16* Qh = (__nv_bfloat16*)smraw;
    __nv_bfloat16* Ql = Qh + 64 * QSTR;
    __nv_bfloat16* Kh = Ql + 64 * QSTR;
    __nv_bfloat16* Kl = Kh + 64 * QSTR;
    __nv_bfloat16* Vh = Kl + 64 * QSTR;
    __nv_bfloat16* Vl = Vh + 64 * QSTR;
    float* delta = (float*)(Vl + 64 * QSTR);   // [64][3]
    float* pde   = delta + 192;                // [64][3] unnorm exp near diag
    float* pdm   = pde + 192;                  // [64][3] max used for pde
    float* srelv = pdm + 192;                  // [4][64]

    const int tid  = threadIdx.x;
    const int w    = tid >> 5, lane = tid & 31;
    const int g    = lane >> 2, tq = lane & 3;
    const int b    = blockIdx.x >> 2;
    const int tile = 3 - (blockIdx.x & 3);
    const int t0   = tile * 64;
    const int nch  = tile + 1;

    const __nv_bfloat16* gqh = g_qh + (size_t)b * 16384 + (size_t)t0 * 64;
    const __nv_bfloat16* gql = g_ql + (size_t)b * 16384 + (size_t)t0 * 64;

    // ---- load Q tile (hi/lo), preload relv, init pdiag ----
    for (int i = tid; i < 512; i += 128) {
        int r = i >> 3, seg = i & 7;
        *(uint4*)&Qh[r * QSTR + seg * 8] = *(const uint4*)&gqh[r * 64 + seg * 8];
        *(uint4*)&Ql[r * QSTR + seg * 8] = *(const uint4*)&gql[r * 64 + seg * 8];
    }
    for (int i = tid; i < 256; i += 128) srelv[i] = relv[i];
    for (int i = tid; i < 192; i += 128) { pde[i] = 0.f; pdm[i] = 0.f; }
    __syncthreads();

    // ---- delta[r][j] = q_scaled . (relk[j+1] - relk[0]), j = (s-t)+2 ----
    for (int idx = tid; idx < 192; idx += 128) {
        int r = idx / 3, j = idx - r * 3;
        const float* rkd = relk + (j + 1) * 64;
        float s = 0.f;
#pragma unroll 8
        for (int h = 0; h < 64; h++) {
            float qv = __bfloat162float(Qh[r * QSTR + h]) + __bfloat162float(Ql[r * QSTR + h]);
            s += qv * (rkd[h] - relk[h]);
        }
        delta[idx] = s;
    }

    // ---- Q A-frags in registers ----
    uint32_t qfh[4][4], qfl[4][4];
    const int rl_lo = w * 16 + g, rl_hi = rl_lo + 8;
    const int tlo = t0 + rl_lo, thi = t0 + rl_hi;
#pragma unroll
    for (int ks = 0; ks < 4; ks++) {
        int ka = ks * 16 + 2 * tq;
        qfh[ks][0] = lds32(Qh + rl_lo * QSTR + ka);
        qfh[ks][1] = lds32(Qh + rl_hi * QSTR + ka);
        qfh[ks][2] = lds32(Qh + rl_lo * QSTR + ka + 8);
        qfh[ks][3] = lds32(Qh + rl_hi * QSTR + ka + 8);
        qfl[ks][0] = lds32(Ql + rl_lo * QSTR + ka);
        qfl[ks][1] = lds32(Ql + rl_hi * QSTR + ka);
        qfl[ks][2] = lds32(Ql + rl_lo * QSTR + ka + 8);
        qfl[ks][3] = lds32(Ql + rl_hi * QSTR + ka + 8);
    }

    float m0 = -1e30f, m1 = -1e30f, l0 = 0.f, l1 = 0.f;
    float O[8][4];
#pragma unroll
    for (int ht = 0; ht < 8; ht++)
#pragma unroll
        for (int e = 0; e < 4; e++) O[ht][e] = 0.f;

    for (int c = 0; c < nch; c++) {
        __syncthreads();
        const __nv_bfloat16* kh = g_kh + (size_t)b * 16384 + (size_t)c * 4096;
        const __nv_bfloat16* kl = g_kl + (size_t)b * 16384 + (size_t)c * 4096;
        const __nv_bfloat16* vh = g_vth + (size_t)b * 16384 + c * 64;
        const __nv_bfloat16* vl = g_vtl + (size_t)b * 16384 + c * 64;
        for (int i = tid; i < 512; i += 128) {
            int r = i >> 3, seg = i & 7;
            *(uint4*)&Kh[r * QSTR + seg * 8] = *(const uint4*)&kh[r * 64 + seg * 8];
            *(uint4*)&Kl[r * QSTR + seg * 8] = *(const uint4*)&kl[r * 64 + seg * 8];
            *(uint4*)&Vh[r * QSTR + seg * 8] = *(const uint4*)&vh[r * 256 + seg * 8];
            *(uint4*)&Vl[r * QSTR + seg * 8] = *(const uint4*)&vl[r * 256 + seg * 8];
        }
        __syncthreads();

        // ---- QK^T: 3 split passes ----
        float C[8][4];
#pragma unroll
        for (int nt = 0; nt < 8; nt++) {
            C[nt][0] = C[nt][1] = C[nt][2] = C[nt][3] = 0.f;
            uint32_t bh[4][2], bl[4][2];
            int krow = nt * 8 + g;
#pragma unroll
            for (int ks = 0; ks < 4; ks++) {
                int ka = ks * 16 + 2 * tq;
                bh[ks][0] = lds32(Kh + krow * QSTR + ka);
                bh[ks][1] = lds32(Kh + krow * QSTR + ka + 8);
                bl[ks][0] = lds32(Kl + krow * QSTR + ka);
                bl[ks][1] = lds32(Kl + krow * QSTR + ka + 8);
            }
#pragma unroll
            for (int ks = 0; ks < 4; ks++) hmma(C[nt], qfh[ks], bh[ks]);
#pragma unroll
            for (int ks = 0; ks < 4; ks++) hmma(C[nt], qfl[ks], bh[ks]);
#pragma unroll
            for (int ks = 0; ks < 4; ks++) hmma(C[nt], qfh[ks], bl[ks]);
        }

        // ---- mask + delta-bias + chunk max ----
        float mx0 = -1e30f, mx1 = -1e30f;
#pragma unroll
        for (int nt = 0; nt < 8; nt++) {
            int sb = c * 64 + nt * 8 + 2 * tq;
            int r0 = sb - tlo, r2 = sb - thi;
            if (r0 > 0)            C[nt][0] = -1e30f;
            else if (r0 >= -2)     C[nt][0] += delta[rl_lo * 3 + r0 + 2];
            if (r0 + 1 > 0)        C[nt][1] = -1e30f;
            else if (r0 + 1 >= -2) C[nt][1] += delta[rl_lo * 3 + r0 + 3];
            if (r2 > 0)            C[nt][2] = -1e30f;
            else if (r2 >= -2)     C[nt][2] += delta[rl_hi * 3 + r2 + 2];
            if (r2 + 1 > 0)        C[nt][3] = -1e30f;
            else if (r2 + 1 >= -2) C[nt][3] += delta[rl_hi * 3 + r2 + 3];
            mx0 = fmaxf(mx0, fmaxf(C[nt][0], C[nt][1]));
            mx1 = fmaxf(mx1, fmaxf(C[nt][2], C[nt][3]));
        }
        mx0 = fmaxf(mx0, __shfl_xor_sync(~0u, mx0, 1));
        mx0 = fmaxf(mx0, __shfl_xor_sync(~0u, mx0, 2));
        mx1 = fmaxf(mx1, __shfl_xor_sync(~0u, mx1, 1));
        mx1 = fmaxf(mx1, __shfl_xor_sync(~0u, mx1, 2));
        float nm0 = fmaxf(m0, mx0), nm1 = fmaxf(m1, mx1);
        float rs0 = ex2(m0 - nm0), rs1 = ex2(m1 - nm1);
        m0 = nm0; m1 = nm1;
        l0 *= rs0; l1 *= rs1;
#pragma unroll
        for (int ht = 0; ht < 8; ht++) {
            O[ht][0] *= rs0; O[ht][1] *= rs0; O[ht][2] *= rs1; O[ht][3] *= rs1;
        }

        // ---- exp2, sums, pdiag capture, pack P to bf16 hi/lo frags ----
        uint32_t ph[8][2], pl[8][2];
        float sa0 = 0.f, sa1 = 0.f;
#pragma unroll
        for (int nt = 0; nt < 8; nt++) {
            float e0 = ex2(C[nt][0] - m0), e1 = ex2(C[nt][1] - m0);
            float e2 = ex2(C[nt][2] - m1), e3 = ex2(C[nt][3] - m1);
            sa0 += e0 + e1; sa1 += e2 + e3;
            int sb = c * 64 + nt * 8 + 2 * tq;
            int r0 = sb - tlo, r2 = sb - thi;
            if ((unsigned)(r0 + 2) <= 2u) { pde[rl_lo * 3 + r0 + 2] = e0; pdm[rl_lo * 3 + r0 + 2] = m0; }
            if ((unsigned)(r0 + 3) <= 2u) { pde[rl_lo * 3 + r0 + 3] = e1; pdm[rl_lo * 3 + r0 + 3] = m0; }
            if ((unsigned)(r2 + 2) <= 2u) { pde[rl_hi * 3 + r2 + 2] = e2; pdm[rl_hi * 3 + r2 + 2] = m1; }
            if ((unsigned)(r2 + 3) <= 2u) { pde[rl_hi * 3 + r2 + 3] = e3; pdm[rl_hi * 3 + r2 + 3] = m1; }
            __nv_bfloat162 h01 = __floats2bfloat162_rn(e0, e1);
            float2 hf01 = __bfloat1622float2(h01);
            __nv_bfloat162 l01 = __floats2bfloat162_rn(e0 - hf01.x, e1 - hf01.y);
            __nv_bfloat162 h23 = __floats2bfloat162_rn(e2, e3);
            float2 hf23 = __bfloat1622float2(h23);
            __nv_bfloat162 l23 = __floats2bfloat162_rn(e2 - hf23.x, e3 - hf23.y);
            ph[nt][0] = b2u(h01); ph[nt][1] = b2u(h23);
            pl[nt][0] = b2u(l01); pl[nt][1] = b2u(l23);
        }
        sa0 += __shfl_xor_sync(~0u, sa0, 1); sa0 += __shfl_xor_sync(~0u, sa0, 2);
        sa1 += __shfl_xor_sync(~0u, sa1, 1); sa1 += __shfl_xor_sync(~0u, sa1, 2);
        l0 += sa0; l1 += sa1;

        // ---- PV: 3 split passes ----
#pragma unroll
        for (int ht = 0; ht < 8; ht++) {
            uint32_t vbh[4][2], vbl[4][2];
            int hrow = ht * 8 + g;
#pragma unroll
            for (int ks = 0; ks < 4; ks++) {
                int ka = ks * 16 + 2 * tq;
                vbh[ks][0] = lds32(Vh + hrow * QSTR + ka);
                vbh[ks][1] = lds32(Vh + hrow * QSTR + ka + 8);
                vbl[ks][0] = lds32(Vl + hrow * QSTR + ka);
                vbl[ks][1] = lds32(Vl + hrow * QSTR + ka + 8);
            }
#pragma unroll
            for (int ks = 0; ks < 4; ks++) {
                uint32_t pa[4] = {ph[2 * ks][0], ph[2 * ks][1], ph[2 * ks + 1][0], ph[2 * ks + 1][1]};
                hmma(O[ht], pa, vbh[ks]);
            }
#pragma unroll
            for (int ks = 0; ks < 4; ks++) {
                uint32_t pa[4] = {pl[2 * ks][0], pl[2 * ks][1], pl[2 * ks + 1][0], pl[2 * ks + 1][1]};
                hmma(O[ht], pa, vbh[ks]);
            }
#pragma unroll
            for (int ks = 0; ks < 4; ks++) {
                uint32_t pa[4] = {ph[2 * ks][0], ph[2 * ks][1], ph[2 * ks + 1][0], ph[2 * ks + 1][1]};
                hmma(O[ht], pa, vbl[ks]);
            }
        }
    }
    __syncwarp();

    // ---- epilogue: normalize + collapsed rel_v correction ----
    float inv0 = 1.f / l0, inv1 = 1.f / l1;
    float pA0 = pde[rl_lo * 3 + 0] * ex2(pdm[rl_lo * 3 + 0] - m0) * inv0;  // s=t-2
    float pA1 = pde[rl_lo * 3 + 1] * ex2(pdm[rl_lo * 3 + 1] - m0) * inv0;  // s=t-1
    float pA2 = pde[rl_lo * 3 + 2] * ex2(pdm[rl_lo * 3 + 2] - m0) * inv0;  // s=t
    float aw0A = 1.f - pA0 - pA1 - pA2;
    float pB0 = pde[rl_hi * 3 + 0] * ex2(pdm[rl_hi * 3 + 0] - m1) * inv1;
    float pB1 = pde[rl_hi * 3 + 1] * ex2(pdm[rl_hi * 3 + 1] - m1) * inv1;
    float pB2 = pde[rl_hi * 3 + 2] * ex2(pdm[rl_hi * 3 + 2] - m1) * inv1;
    float aw0B = 1.f - pB0 - pB1 - pB2;

#pragma unroll
    for (int ht = 0; ht < 8; ht++) {
        int h = ht * 8 + 2 * tq;
        float w2a0 = aw0A * srelv[h]     + pA0 * srelv[64 + h]
                   + pA1 * srelv[128 + h] + pA2 * srelv[192 + h];
        float w2a1 = aw0A * srelv[h + 1] + pA0 * srelv[64 + h + 1]
                   + pA1 * srelv[128 + h + 1] + pA2 * srelv[192 + h + 1];
        float w2b0 = aw0B * srelv[h]     + pB0 * srelv[64 + h]
                   + pB1 * srelv[128 + h] + pB2 * srelv[192 + h];
        float w2b1 = aw0B * srelv[h + 1] + pB0 * srelv[64 + h + 1]
                   + pB1 * srelv[128 + h + 1] + pB2 * srelv[192 + h + 1];
        *(float2*)&out[((size_t)b * 256 + tlo) * 64 + h] =
            make_float2(O[ht][0] * inv0 + w2a0, O[ht][1] * inv0 + w2a1);
        *(float2*)&out[((size_t)b * 256 + thi) * 64 + h] =
            make_float2(O[ht][2] * inv1 + w2b0, O[ht][3] * inv1 + w2b1);
    }
}

// ============================================================================
extern "C" void kernel_launch(void* const* d_in, const int* in_sizes, int n_in,
                              void* d_out, int out_size) {
    const float* x    = (const float*)d_in[0];
    const float* Wq   = (const float*)d_in[1];
    const float* Wk   = (const float*)d_in[2];
    const float* Wv   = (const float*)d_in[3];
    const float* relk = (const float*)d_in[4];
    const float* relv = (const float*)d_in[5];
    float* out = (float*)d_out;

    prep_w<<<(Cc * NB + 255) / 256, 256>>>(Wq, Wk, Wv);

    int gemm_smem = (2 * 128 * ASTR + 2 * 192 * ASTR) * (int)sizeof(__nv_bfloat16);
    cudaFuncSetAttribute(qkv_hmma, cudaFuncAttributeMaxDynamicSharedMemorySize, gemm_smem);
    qkv_hmma<<<(Bb * Tt) / 128, 256, gemm_smem>>>(x);

    int attn_smem = 6 * 64 * QSTR * (int)sizeof(__nv_bfloat16)
                  + (192 + 192 + 192 + 256) * (int)sizeof(float);
    cudaFuncSetAttribute(attn_flash, cudaFuncAttributeMaxDynamicSharedMemorySize, attn_smem);
    attn_flash<<<Bb * 4, 128, attn_smem>>>(relk, relv, out);
}

// round 5
// speedup vs baseline: 3.8943x; 1.1014x over previous
#include <cuda_runtime.h>
#include <cuda_bf16.h>
#include <cstdint>

#define Bb 256
#define Tt 256
#define Cc 384
#define Hh 64
#define NB 192

// q pre-scale: 1/sqrt(64) * log2(e)  -> scores come out in exp2 domain
#define SCL 0.18033688011112042f

// Scratch (device globals per harness rules). q/k: [b][t][h]; vT: [b][h][t]
__device__ __align__(16) __nv_bfloat16 g_qh[Bb*Tt*Hh];
__device__ __align__(16) __nv_bfloat16 g_ql[Bb*Tt*Hh];
__device__ __align__(16) __nv_bfloat16 g_kh[Bb*Tt*Hh];
__device__ __align__(16) __nv_bfloat16 g_kl[Bb*Tt*Hh];
__device__ __align__(16) __nv_bfloat16 g_vth[Bb*Tt*Hh];
__device__ __align__(16) __nv_bfloat16 g_vtl[Bb*Tt*Hh];
__device__ __align__(16) __nv_bfloat16 g_bh[NB*Cc];     // W^T hi, K-major rows
__device__ __align__(16) __nv_bfloat16 g_bl[NB*Cc];     // W^T lo
__device__ __align__(16) __nv_bfloat16 g_xh[Bb*Tt*Cc];  // x hi
__device__ __align__(16) __nv_bfloat16 g_xl[Bb*Tt*Cc];  // x lo

// ---------------- helpers ----------------
static __device__ __forceinline__ void hmma(float* c, const uint32_t* a, const uint32_t* b) {
    asm volatile(
        "mma.sync.aligned.m16n8k16.row.col.f32.bf16.bf16.f32 "
        "{%0,%1,%2,%3}, {%4,%5,%6,%7}, {%8,%9}, {%0,%1,%2,%3};"
        : "+f"(c[0]), "+f"(c[1]), "+f"(c[2]), "+f"(c[3])
        : "r"(a[0]), "r"(a[1]), "r"(a[2]), "r"(a[3]), "r"(b[0]), "r"(b[1]));
}
static __device__ __forceinline__ uint32_t lds32(const __nv_bfloat16* p) {
    return *(const uint32_t*)p;
}
static __device__ __forceinline__ float ex2(float x) {
    float r;
    asm("ex2.approx.ftz.f32 %0, %1;" : "=f"(r) : "f"(x));
    return r;
}
static __device__ __forceinline__ uint32_t b2u(__nv_bfloat162 v) {
    return *(uint32_t*)&v;
}
static __device__ __forceinline__ uint32_t smem_u32(const void* p) {
    uint32_t a;
    asm("{ .reg .u64 t; cvta.to.shared.u64 t, %1; cvt.u32.u64 %0, t; }" : "=r"(a) : "l"(p));
    return a;
}
static __device__ __forceinline__ void cp16(uint32_t dst, const void* src) {
    asm volatile("cp.async.cg.shared.global [%0], [%1], 16;" :: "r"(dst), "l"(src) : "memory");
}
static __device__ __forceinline__ void ldmx4(uint32_t* r, uint32_t addr) {
    asm volatile("ldmatrix.sync.aligned.m8n8.x4.shared.b16 {%0,%1,%2,%3}, [%4];"
                 : "=r"(r[0]), "=r"(r[1]), "=r"(r[2]), "=r"(r[3]) : "r"(addr));
}

// ============================================================================
// Kernel 0a: split W into K-major bf16 hi/lo
// ============================================================================
__global__ __launch_bounds__(256) void prep_w(const float* __restrict__ Wq,
                                              const float* __restrict__ Wk,
                                              const float* __restrict__ Wv) {
    int j = blockIdx.x * 256 + threadIdx.x;
    if (j >= Cc * NB) return;
    int k = j / NB, n = j - k * NB;
    const float* w = (n < 64) ? Wq : ((n < 128) ? Wk : Wv);
    float v = w[k * 64 + (n & 63)];
    __nv_bfloat16 hi = __float2bfloat16(v);
    float lo = v - __bfloat162float(hi);
    g_bh[n * Cc + k] = hi;
    g_bl[n * Cc + k] = __float2bfloat16(lo);
}

// ============================================================================
// Kernel 0b: split x into bf16 hi/lo (row-major [b*t][k])
// ============================================================================
__global__ __launch_bounds__(256) void prep_x(const float* __restrict__ x) {
    size_t i = (size_t)blockIdx.x * 256 + threadIdx.x;   // 4 elems each
    float4 v = ((const float4*)x)[i];
    __nv_bfloat162 h0 = __floats2bfloat162_rn(v.x, v.y);
    __nv_bfloat162 h1 = __floats2bfloat162_rn(v.z, v.w);
    float2 f0 = __bfloat1622float2(h0), f1 = __bfloat1622float2(h1);
    __nv_bfloat162 l0 = __floats2bfloat162_rn(v.x - f0.x, v.y - f0.y);
    __nv_bfloat162 l1 = __floats2bfloat162_rn(v.z - f1.x, v.w - f1.y);
    uint2 hp, lp;
    hp.x = b2u(h0); hp.y = b2u(h1);
    lp.x = b2u(l0); lp.y = b2u(l1);
    ((uint2*)g_xh)[i] = hp;
    ((uint2*)g_xl)[i] = lp;
}

// ============================================================================
// Kernel 1: QKV projection — cp.async double-buffered, ldmatrix-fed HMMA.
// CTA tile M=128 x N=192, K=384 in 6 chunks of 64, 2 smem stages.
// ============================================================================
#define ASTR 72
#define STGE (640 * ASTR)          // bf16 elems/stage: (128+128+192+192)*72
__global__ __launch_bounds__(256) void qkv_hmma() {
    extern __shared__ __nv_bfloat16 sm[];
    const uint32_t sb = smem_u32(sm);

    const int tid  = threadIdx.x;
    const int wid  = tid >> 5, lane = tid & 31;
    const int g    = lane >> 2, t = lane & 3;
    const int wm   = wid & 3;
    const int wn   = wid >> 2;
    const int row0 = blockIdx.x * 128;

    // ldmatrix per-lane address components
    const int aRow = (lane & 7) + (((lane >> 3) & 1) << 3);
    const int aCol = (lane >> 4) << 3;
    const int bRow = (lane & 7) + ((lane >> 4) << 3);
    const int bCol = ((lane >> 3) & 1) << 3;

    float acc[2][12][4];
#pragma unroll
    for (int mi = 0; mi < 2; mi++)
#pragma unroll
        for (int ni = 0; ni < 12; ni++)
#pragma unroll
            for (int e = 0; e < 4; e++) acc[mi][ni][e] = 0.f;

    // ---- async copy of one K-chunk into stage st ----
    auto issue = [&](int c, int st) {
        const int k0 = c * 64;
        const uint32_t sB = sb + (uint32_t)st * STGE * 2;
#pragma unroll
        for (int i = tid; i < 1024; i += 256) {          // A: 128 rows x 8 segs
            int r = i >> 3, seg = i & 7;
            uint32_t d = sB + (uint32_t)(r * ASTR + seg * 8) * 2;
            cp16(d,                  g_xh + (size_t)(row0 + r) * Cc + k0 + seg * 8);
            cp16(d + 128 * ASTR * 2, g_xl + (size_t)(row0 + r) * Cc + k0 + seg * 8);
        }
#pragma unroll
        for (int i = tid; i < 1536; i += 256) {          // B: 192 rows x 8 segs
            int n = i >> 3, seg = i & 7;
            uint32_t d = sB + (uint32_t)(256 * ASTR + n * ASTR + seg * 8) * 2;
            cp16(d,                  g_bh + (size_t)n * Cc + k0 + seg * 8);
            cp16(d + 192 * ASTR * 2, g_bl + (size_t)n * Cc + k0 + seg * 8);
        }
        asm volatile("cp.async.commit_group;" ::: "memory");
    };

    issue(0, 0);
    for (int c = 0; c < 6; c++) {
        if (c < 5) {
            issue(c + 1, (c + 1) & 1);
            asm volatile("cp.async.wait_group 1;" ::: "memory");
        } else {
            asm volatile("cp.async.wait_group 0;" ::: "memory");
        }
        __syncthreads();

        const int st = c & 1;
        const uint32_t base = sb + (uint32_t)st * STGE * 2;
        const uint32_t AhB = base;
        const uint32_t AlB = base + 128 * ASTR * 2;
        const uint32_t BhB = base + 256 * ASTR * 2;
        const uint32_t BlB = base + 448 * ASTR * 2;

#pragma unroll
        for (int s = 0; s < 4; s++) {
            const int ka = s * 16;
            uint32_t ah[2][4], al[2][4];
#pragma unroll
            for (int mi = 0; mi < 2; mi++) {
                uint32_t ao = (uint32_t)((wm * 32 + mi * 16 + aRow) * ASTR + ka + aCol) * 2;
                ldmx4(ah[mi], AhB + ao);
                ldmx4(al[mi], AlB + ao);
            }
#pragma unroll
            for (int nj = 0; nj < 6; nj++) {
                uint32_t bfh[4], bfl[4];
                uint32_t bo = (uint32_t)((wn * 96 + nj * 16 + bRow) * ASTR + ka + bCol) * 2;
                ldmx4(bfh, BhB + bo);
                ldmx4(bfl, BlB + bo);
#pragma unroll
                for (int mi = 0; mi < 2; mi++) {
                    hmma(acc[mi][2 * nj],     ah[mi], bfh);       // hi*hi
                    hmma(acc[mi][2 * nj + 1], ah[mi], bfh + 2);
                    hmma(acc[mi][2 * nj],     al[mi], bfh);       // lo*hi
                    hmma(acc[mi][2 * nj + 1], al[mi], bfh + 2);
                    hmma(acc[mi][2 * nj],     ah[mi], bfl);       // hi*lo
                    hmma(acc[mi][2 * nj + 1], ah[mi], bfl + 2);
                }
            }
        }
        __syncthreads();
    }

    // ---- epilogue: split to bf16 hi/lo and scatter (q scaled, v transposed) ----
#pragma unroll
    for (int mi = 0; mi < 2; mi++) {
        int r = row0 + wm * 32 + mi * 16 + g;
        int bI = r >> 8, tt = r & 255;
#pragma unroll
        for (int ni = 0; ni < 12; ni++) {
            int col = wn * 96 + ni * 8 + 2 * t;
            float v00 = acc[mi][ni][0], v01 = acc[mi][ni][1];
            float v10 = acc[mi][ni][2], v11 = acc[mi][ni][3];
            if (col < 64) { v00 *= SCL; v01 *= SCL; v10 *= SCL; v11 *= SCL; }
            __nv_bfloat162 h0 = __floats2bfloat162_rn(v00, v01);
            float2 hf0 = __bfloat1622float2(h0);
            __nv_bfloat162 l0 = __floats2bfloat162_rn(v00 - hf0.x, v01 - hf0.y);
            __nv_bfloat162 h1 = __floats2bfloat162_rn(v10, v11);
            float2 hf1 = __bfloat1622float2(h1);
            __nv_bfloat162 l1 = __floats2bfloat162_rn(v10 - hf1.x, v11 - hf1.y);
            if (col < 128) {
                __nv_bfloat16* dh = (col < 64) ? g_qh : g_kh;
                __nv_bfloat16* dl = (col < 64) ? g_ql : g_kl;
                int cc = col & 63;
                *(__nv_bfloat162*)&dh[(size_t)r * 64 + cc]       = h0;
                *(__nv_bfloat162*)&dl[(size_t)r * 64 + cc]       = l0;
                *(__nv_bfloat162*)&dh[(size_t)(r + 8) * 64 + cc] = h1;
                *(__nv_bfloat162*)&dl[(size_t)(r + 8) * 64 + cc] = l1;
            } else {
                int cc = col - 128;
                size_t base = (size_t)bI * 16384 + (size_t)cc * 256;
                g_vth[base + tt]           = h0.x;
                g_vth[base + 256 + tt]     = h0.y;
                g_vtl[base + tt]           = l0.x;
                g_vtl[base + 256 + tt]     = l0.y;
                g_vth[base + tt + 8]       = h1.x;
                g_vth[base + 256 + tt + 8] = h1.y;
                g_vtl[base + tt + 8]       = l1.x;
                g_vtl[base + 256 + tt + 8] = l1.y;
            }
        }
    }
}

// ============================================================================
// Kernel 2: flash-style causal attention (unchanged from passing R4 version)
// ============================================================================
#define QSTR 72
__global__ __launch_bounds__(128, 3) void attn_flash(const float* __restrict__ relk,
                                                     const float* __restrict__ relv,
                                                     float* __restrict__ out) {
    extern __shared__ char smraw[];
    __nv_bfloat16* Qh = (__nv_bfloat16*)smraw;
    __nv_bfloat16* Ql = Qh + 64 * QSTR;
    __nv_bfloat16* Kh = Ql + 64 * QSTR;
    __nv_bfloat16* Kl = Kh + 64 * QSTR;
    __nv_bfloat16* Vh = Kl + 64 * QSTR;
    __nv_bfloat16* Vl = Vh + 64 * QSTR;
    float* delta = (float*)(Vl + 64 * QSTR);   // [64][3]
    float* pde   = delta + 192;                // [64][3]
    float* pdm   = pde + 192;                  // [64][3]
    float* srelv = pdm + 192;                  // [4][64]

    const int tid  = threadIdx.x;
    const int w    = tid >> 5, lane = tid & 31;
    const int g    = lane >> 2, tq = lane & 3;
    const int b    = blockIdx.x >> 2;
    const int tile = 3 - (blockIdx.x & 3);
    const int t0   = tile * 64;
    const int nch  = tile + 1;

    const __nv_bfloat16* gqh = g_qh + (size_t)b * 16384 + (size_t)t0 * 64;
    const __nv_bfloat16* gql = g_ql + (size_t)b * 16384 + (size_t)t0 * 64;

    for (int i = tid; i < 512; i += 128) {
        int r = i >> 3, seg = i & 7;
        *(uint4*)&Qh[r * QSTR + seg * 8] = *(const uint4*)&gqh[r * 64 + seg * 8];
        *(uint4*)&Ql[r * QSTR + seg * 8] = *(const uint4*)&gql[r * 64 + seg * 8];
    }
    for (int i = tid; i < 256; i += 128) srelv[i] = relv[i];
    for (int i = tid; i < 192; i += 128) { pde[i] = 0.f; pdm[i] = 0.f; }
    __syncthreads();

    for (int idx = tid; idx < 192; idx += 128) {
        int r = idx / 3, j = idx - r * 3;
        const float* rkd = relk + (j + 1) * 64;
        float s = 0.f;
#pragma unroll 8
        for (int h = 0; h < 64; h++) {
            float qv = __bfloat162float(Qh[r * QSTR + h]) + __bfloat162float(Ql[r * QSTR + h]);
            s += qv * (rkd[h] - relk[h]);
        }
        delta[idx] = s;
    }

    uint32_t qfh[4][4], qfl[4][4];
    const int rl_lo = w * 16 + g, rl_hi = rl_lo + 8;
    const int tlo = t0 + rl_lo, thi = t0 + rl_hi;
#pragma unroll
    for (int ks = 0; ks < 4; ks++) {
        int ka = ks * 16 + 2 * tq;
        qfh[ks][0] = lds32(Qh + rl_lo * QSTR + ka);
        qfh[ks][1] = lds32(Qh + rl_hi * QSTR + ka);
        qfh[ks][2] = lds32(Qh + rl_lo * QSTR + ka + 8);
        qfh[ks][3] = lds32(Qh + rl_hi * QSTR + ka + 8);
        qfl[ks][0] = lds32(Ql + rl_lo * QSTR + ka);
        qfl[ks][1] = lds32(Ql + rl_hi * QSTR + ka);
        qfl[ks][2] = lds32(Ql + rl_lo * QSTR + ka + 8);
        qfl[ks][3] = lds32(Ql + rl_hi * QSTR + ka + 8);
    }

    float m0 = -1e30f, m1 = -1e30f, l0 = 0.f, l1 = 0.f;
    float O[8][4];
#pragma unroll
    for (int ht = 0; ht < 8; ht++)
#pragma unroll
        for (int e = 0; e < 4; e++) O[ht][e] = 0.f;

    for (int c = 0; c < nch; c++) {
        __syncthreads();
        const __nv_bfloat16* kh = g_kh + (size_t)b * 16384 + (size_t)c * 4096;
        const __nv_bfloat16* kl = g_kl + (size_t)b * 16384 + (size_t)c * 4096;
        const __nv_bfloat16* vh = g_vth + (size_t)b * 16384 + c * 64;
        const __nv_bfloat16* vl = g_vtl + (size_t)b * 16384 + c * 64;
        for (int i = tid; i < 512; i += 128) {
            int r = i >> 3, seg = i & 7;
            *(uint4*)&Kh[r * QSTR + seg * 8] = *(const uint4*)&kh[r * 64 + seg * 8];
            *(uint4*)&Kl[r * QSTR + seg * 8] = *(const uint4*)&kl[r * 64 + seg * 8];
            *(uint4*)&Vh[r * QSTR + seg * 8] = *(const uint4*)&vh[r * 256 + seg * 8];
            *(uint4*)&Vl[r * QSTR + seg * 8] = *(const uint4*)&vl[r * 256 + seg * 8];
        }
        __syncthreads();

        float C[8][4];
#pragma unroll
        for (int nt = 0; nt < 8; nt++) {
            C[nt][0] = C[nt][1] = C[nt][2] = C[nt][3] = 0.f;
            uint32_t bh[4][2], bl[4][2];
            int krow = nt * 8 + g;
#pragma unroll
            for (int ks = 0; ks < 4; ks++) {
                int ka = ks * 16 + 2 * tq;
                bh[ks][0] = lds32(Kh + krow * QSTR + ka);
                bh[ks][1] = lds32(Kh + krow * QSTR + ka + 8);
                bl[ks][0] = lds32(Kl + krow * QSTR + ka);
                bl[ks][1] = lds32(Kl + krow * QSTR + ka + 8);
            }
#pragma unroll
            for (int ks = 0; ks < 4; ks++) hmma(C[nt], qfh[ks], bh[ks]);
#pragma unroll
            for (int ks = 0; ks < 4; ks++) hmma(C[nt], qfl[ks], bh[ks]);
#pragma unroll
            for (int ks = 0; ks < 4; ks++) hmma(C[nt], qfh[ks], bl[ks]);
        }

        float mx0 = -1e30f, mx1 = -1e30f;
#pragma unroll
        for (int nt = 0; nt < 8; nt++) {
            int sb = c * 64 + nt * 8 + 2 * tq;
            int r0 = sb - tlo, r2 = sb - thi;
            if (r0 > 0)            C[nt][0] = -1e30f;
            else if (r0 >= -2)     C[nt][0] += delta[rl_lo * 3 + r0 + 2];
            if (r0 + 1 > 0)        C[nt][1] = -1e30f;
            else if (r0 + 1 >= -2) C[nt][1] += delta[rl_lo * 3 + r0 + 3];
            if (r2 > 0)            C[nt][2] = -1e30f;
            else if (r2 >= -2)     C[nt][2] += delta[rl_hi * 3 + r2 + 2];
            if (r2 + 1 > 0)        C[nt][3] = -1e30f;
            else if (r2 + 1 >= -2) C[nt][3] += delta[rl_hi * 3 + r2 + 3];
            mx0 = fmaxf(mx0, fmaxf(C[nt][0], C[nt][1]));
            mx1 = fmaxf(mx1, fmaxf(C[nt][2], C[nt][3]));
        }
        mx0 = fmaxf(mx0, __shfl_xor_sync(~0u, mx0, 1));
        mx0 = fmaxf(mx0, __shfl_xor_sync(~0u, mx0, 2));
        mx1 = fmaxf(mx1, __shfl_xor_sync(~0u, mx1, 1));
        mx1 = fmaxf(mx1, __shfl_xor_sync(~0u, mx1, 2));
        float nm0 = fmaxf(m0, mx0), nm1 = fmaxf(m1, mx1);
        float rs0 = ex2(m0 - nm0), rs1 = ex2(m1 - nm1);
        m0 = nm0; m1 = nm1;
        l0 *= rs0; l1 *= rs1;
#pragma unroll
        for (int ht = 0; ht < 8; ht++) {
            O[ht][0] *= rs0; O[ht][1] *= rs0; O[ht][2] *= rs1; O[ht][3] *= rs1;
        }

        uint32_t ph[8][2], pl[8][2];
        float sa0 = 0.f, sa1 = 0.f;
#pragma unroll
        for (int nt = 0; nt < 8; nt++) {
            float e0 = ex2(C[nt][0] - m0), e1 = ex2(C[nt][1] - m0);
            float e2 = ex2(C[nt][2] - m1), e3 = ex2(C[nt][3] - m1);
            sa0 += e0 + e1; sa1 += e2 + e3;
            int sb = c * 64 + nt * 8 + 2 * tq;
            int r0 = sb - tlo, r2 = sb - thi;
            if ((unsigned)(r0 + 2) <= 2u) { pde[rl_lo * 3 + r0 + 2] = e0; pdm[rl_lo * 3 + r0 + 2] = m0; }
            if ((unsigned)(r0 + 3) <= 2u) { pde[rl_lo * 3 + r0 + 3] = e1; pdm[rl_lo * 3 + r0 + 3] = m0; }
            if ((unsigned)(r2 + 2) <= 2u) { pde[rl_hi * 3 + r2 + 2] = e2; pdm[rl_hi * 3 + r2 + 2] = m1; }
            if ((unsigned)(r2 + 3) <= 2u) { pde[rl_hi * 3 + r2 + 3] = e3; pdm[rl_hi * 3 + r2 + 3] = m1; }
            __nv_bfloat162 h01 = __floats2bfloat162_rn(e0, e1);
            float2 hf01 = __bfloat1622float2(h01);
            __nv_bfloat162 l01 = __floats2bfloat162_rn(e0 - hf01.x, e1 - hf01.y);
            __nv_bfloat162 h23 = __floats2bfloat162_rn(e2, e3);
            float2 hf23 = __bfloat1622float2(h23);
            __nv_bfloat162 l23 = __floats2bfloat162_rn(e2 - hf23.x, e3 - hf23.y);
            ph[nt][0] = b2u(h01); ph[nt][1] = b2u(h23);
            pl[nt][0] = b2u(l01); pl[nt][1] = b2u(l23);
        }
        sa0 += __shfl_xor_sync(~0u, sa0, 1); sa0 += __shfl_xor_sync(~0u, sa0, 2);
        sa1 += __shfl_xor_sync(~0u, sa1, 1); sa1 += __shfl_xor_sync(~0u, sa1, 2);
        l0 += sa0; l1 += sa1;

#pragma unroll
        for (int ht = 0; ht < 8; ht++) {
            uint32_t vbh[4][2], vbl[4][2];
            int hrow = ht * 8 + g;
#pragma unroll
            for (int ks = 0; ks < 4; ks++) {
                int ka = ks * 16 + 2 * tq;
                vbh[ks][0] = lds32(Vh + hrow * QSTR + ka);
                vbh[ks][1] = lds32(Vh + hrow * QSTR + ka + 8);
                vbl[ks][0] = lds32(Vl + hrow * QSTR + ka);
                vbl[ks][1] = lds32(Vl + hrow * QSTR + ka + 8);
            }
#pragma unroll
            for (int ks = 0; ks < 4; ks++) {
                uint32_t pa[4] = {ph[2 * ks][0], ph[2 * ks][1], ph[2 * ks + 1][0], ph[2 * ks + 1][1]};
                hmma(O[ht], pa, vbh[ks]);
            }
#pragma unroll
            for (int ks = 0; ks < 4; ks++) {
                uint32_t pa[4] = {pl[2 * ks][0], pl[2 * ks][1], pl[2 * ks + 1][0], pl[2 * ks + 1][1]};
                hmma(O[ht], pa, vbh[ks]);
            }
#pragma unroll
            for (int ks = 0; ks < 4; ks++) {
                uint32_t pa[4] = {ph[2 * ks][0], ph[2 * ks][1], ph[2 * ks + 1][0], ph[2 * ks + 1][1]};
                hmma(O[ht], pa, vbl[ks]);
            }
        }
    }
    __syncwarp();

    float inv0 = 1.f / l0, inv1 = 1.f / l1;
    float pA0 = pde[rl_lo * 3 + 0] * ex2(pdm[rl_lo * 3 + 0] - m0) * inv0;
    float pA1 = pde[rl_lo * 3 + 1] * ex2(pdm[rl_lo * 3 + 1] - m0) * inv0;
    float pA2 = pde[rl_lo * 3 + 2] * ex2(pdm[rl_lo * 3 + 2] - m0) * inv0;
    float aw0A = 1.f - pA0 - pA1 - pA2;
    float pB0 = pde[rl_hi * 3 + 0] * ex2(pdm[rl_hi * 3 + 0] - m1) * inv1;
    float pB1 = pde[rl_hi * 3 + 1] * ex2(pdm[rl_hi * 3 + 1] - m1) * inv1;
    float pB2 = pde[rl_hi * 3 + 2] * ex2(pdm[rl_hi * 3 + 2] - m1) * inv1;
    float aw0B = 1.f - pB0 - pB1 - pB2;

#pragma unroll
    for (int ht = 0; ht < 8; ht++) {
        int h = ht * 8 + 2 * tq;
        float w2a0 = aw0A * srelv[h]     + pA0 * srelv[64 + h]
                   + pA1 * srelv[128 + h] + pA2 * srelv[192 + h];
        float w2a1 = aw0A * srelv[h + 1] + pA0 * srelv[64 + h + 1]
                   + pA1 * srelv[128 + h + 1] + pA2 * srelv[192 + h + 1];
        float w2b0 = aw0B * srelv[h]     + pB0 * srelv[64 + h]
                   + pB1 * srelv[128 + h] + pB2 * srelv[192 + h];
        float w2b1 = aw0B * srelv[h + 1] + pB0 * srelv[64 + h + 1]
                   + pB1 * srelv[128 + h + 1] + pB2 * srelv[192 + h + 1];
        *(float2*)&out[((size_t)b * 256 + tlo) * 64 + h] =
            make_float2(O[ht][0] * inv0 + w2a0, O[ht][1] * inv0 + w2a1);
        *(float2*)&out[((size_t)b * 256 + thi) * 64 + h] =
            make_float2(O[ht][2] * inv1 + w2b0, O[ht][3] * inv1 + w2b1);
    }
}

// ============================================================================
extern "C" void kernel_launch(void* const* d_in, const int* in_sizes, int n_in,
                              void* d_out, int out_size) {
    const float* x    = (const float*)d_in[0];
    const float* Wq   = (const float*)d_in[1];
    const float* Wk   = (const float*)d_in[2];
    const float* Wv   = (const float*)d_in[3];
    const float* relk = (const float*)d_in[4];
    const float* relv = (const float*)d_in[5];
    float* out = (float*)d_out;

    prep_w<<<(Cc * NB + 255) / 256, 256>>>(Wq, Wk, Wv);
    prep_x<<<(Bb * Tt * Cc / 4) / 256, 256>>>(x);

    int gemm_smem = 2 * STGE * (int)sizeof(__nv_bfloat16);   // 184320 B
    cudaFuncSetAttribute(qkv_hmma, cudaFuncAttributeMaxDynamicSharedMemorySize, gemm_smem);
    qkv_hmma<<<(Bb * Tt) / 128, 256, gemm_smem>>>();

    int attn_smem = 6 * 64 * QSTR * (int)sizeof(__nv_bfloat16)
                  + (192 + 192 + 192 + 256) * (int)sizeof(float);
    cudaFuncSetAttribute(attn_flash, cudaFuncAttributeMaxDynamicSharedMemorySize, attn_smem);
    attn_flash<<<Bb * 4, 128, attn_smem>>>(relk, relv, out);
}